// round 12
// baseline (speedup 1.0000x reference)
#include <cuda_runtime.h>
#include <cuda_bf16.h>
#include <cstdint>

// ---------------- problem constants ----------------
#define BATCH 8192
#define CDIM  4096
#define FDIM  1024
#define ODIM  10

// ---------------- tile config ----------------
#define BM 128
#define BN 128
#define BK 64                 // bf16 elements per K chunk (= 128 bytes per row)
#define KSTEPS (FDIM / BK)    // 16 chunks
#define NCT (CDIM / BN)       // 32 c-tiles
#define NBT (BATCH / BM)      // 64 b-tiles
#define THREADS 128           // 4 warps, each owns a 64x64 warp tile

// ---------------- smem layout (bytes, dynamic) ----------------
#define SM_ABUF(b)  ((b) * 32768)
#define SM_BBUF(b)  ((b) * 32768 + 16384)
#define SM_WPACK    65536                   // float [128][12]  (w repacked, padded)
#define SM_C2IV     (SM_WPACK + 6144)       // float2 [128] (c2, 1/scale)
#define SM_X2       (SM_C2IV + 1024)        // float  [128]
#define SMEM_TOTAL  (SM_X2 + 512)           // 73216 B -> 2 CTAs/SM
// sout (float[128][10]) reuses the dead A0 buffer after the mainloop.

// -------- scratch (device globals; allocation-free) --------
__device__ __nv_bfloat16 g_xb[(size_t)BATCH * FDIM];   // 16 MB
__device__ __nv_bfloat16 g_locb[(size_t)CDIM * FDIM];  //  8 MB
__device__ float g_x2[BATCH];
__device__ float g_c2[CDIM];
__device__ float g_invs[CDIM];
__device__ float g_partial[(size_t)NCT * BATCH * ODIM]; // 10.5 MB

// ---------------- PTX helpers ----------------
__device__ __forceinline__ uint32_t smem_u32(const void* p) {
    uint32_t a;
    asm("{ .reg .u64 t; cvta.to.shared.u64 t, %1; cvt.u32.u64 %0, t; }" : "=r"(a) : "l"(p));
    return a;
}
__device__ __forceinline__ void cp16(uint32_t dst, const void* src) {
    asm volatile("cp.async.cg.shared.global [%0], [%1], 16;" :: "r"(dst), "l"(src));
}
#define CP_COMMIT() asm volatile("cp.async.commit_group;" ::: "memory")
#define CP_WAIT1()  asm volatile("cp.async.wait_group 1;" ::: "memory")

#define LDSM4(r0, r1, r2, r3, addr) \
    asm volatile("ldmatrix.sync.aligned.m8n8.x4.shared.b16 {%0,%1,%2,%3}, [%4];" \
                 : "=r"(r0), "=r"(r1), "=r"(r2), "=r"(r3) : "r"(addr))

__device__ __forceinline__ void mma_bf16(float c[4], const uint32_t a[4],
                                         uint32_t b0, uint32_t b1) {
    asm volatile(
        "mma.sync.aligned.m16n8k16.row.col.f32.bf16.bf16.f32 "
        "{%0,%1,%2,%3}, {%4,%5,%6,%7}, {%8,%9}, {%0,%1,%2,%3};\n"
        : "+f"(c[0]), "+f"(c[1]), "+f"(c[2]), "+f"(c[3])
        : "r"(a[0]), "r"(a[1]), "r"(a[2]), "r"(a[3]), "r"(b0), "r"(b1));
}

// ---------------- pre-pass: fp32 -> bf16 + row norms ----------------
__global__ void conv_x_kernel(const float* __restrict__ x) {
    int row = blockIdx.x, tid = threadIdx.x;
    float4 v = ((const float4*)(x + (size_t)row * FDIM))[tid];
    float s = v.x * v.x + v.y * v.y + v.z * v.z + v.w * v.w;
    __nv_bfloat162* d = (__nv_bfloat162*)(g_xb + (size_t)row * FDIM);
    d[tid * 2 + 0] = __floats2bfloat162_rn(v.x, v.y);
    d[tid * 2 + 1] = __floats2bfloat162_rn(v.z, v.w);
    #pragma unroll
    for (int off = 16; off; off >>= 1) s += __shfl_xor_sync(0xffffffffu, s, off);
    __shared__ float wsum[8];
    if ((tid & 31) == 0) wsum[tid >> 5] = s;
    __syncthreads();
    if (tid == 0) {
        float t = 0.f;
        #pragma unroll
        for (int i = 0; i < 8; i++) t += wsum[i];
        g_x2[row] = t;
    }
}

__global__ void conv_loc_kernel(const float* __restrict__ loc) {
    int row = blockIdx.x, tid = threadIdx.x;
    float4 v = ((const float4*)(loc + (size_t)row * FDIM))[tid];
    float s = v.x * v.x + v.y * v.y + v.z * v.z + v.w * v.w;
    __nv_bfloat162* d = (__nv_bfloat162*)(g_locb + (size_t)row * FDIM);
    d[tid * 2 + 0] = __floats2bfloat162_rn(v.x, v.y);
    d[tid * 2 + 1] = __floats2bfloat162_rn(v.z, v.w);
    #pragma unroll
    for (int off = 16; off; off >>= 1) s += __shfl_xor_sync(0xffffffffu, s, off);
    __shared__ float wsum[8];
    if ((tid & 31) == 0) wsum[tid >> 5] = s;
    __syncthreads();
    if (tid == 0) {
        float t = 0.f;
        #pragma unroll
        for (int i = 0; i < 8; i++) t += wsum[i];
        g_c2[row] = t;
    }
}

__global__ void invs_kernel(const float* __restrict__ scale) {
    int i = blockIdx.x * 256 + threadIdx.x;
    if (i < CDIM) g_invs[i] = 1.0f / scale[i];
}

// ---------------- main fused kernel: mma.sync 64x64 warp tiles ----------------
// CTA = 128x128 tile. 4 warps as 2(m) x 2(n): warp tile 64x64.
__global__ __launch_bounds__(THREADS, 2)
void rbf_main_kernel(const float* __restrict__ w) {
    extern __shared__ char smem[];
    const uint32_t sbase = smem_u32(smem);
    const int tid = threadIdx.x;
    const int lane = tid & 31;
    const int warp = tid >> 5;
    const int wm = warp >> 1;   // m offset wm*64
    const int wn = warp & 1;    // n offset wn*64
    const int bt = blockIdx.x;
    const int ct = blockIdx.y;

    // stage epilogue params into smem
    float*  wpack = (float*)(smem + SM_WPACK);   // [128][12]
    float2* c2iv  = (float2*)(smem + SM_C2IV);   // [128]
    float*  x2s   = (float*)(smem + SM_X2);      // [128]
    for (int i = tid; i < BN * ODIM; i += THREADS) {
        int c = i / ODIM, o = i % ODIM;
        wpack[c * 12 + o] = w[(size_t)o * CDIM + ct * BN + c];
    }
    if (tid < BN) c2iv[tid] = make_float2(g_c2[ct * BN + tid], g_invs[ct * BN + tid]);
    if (tid < BM) x2s[tid] = g_x2[bt * BM + tid];

    // ---- precomputed loader addressing (loop-invariant swizzle) ----
    // 128 threads: r0 = tid>>3 (0..15), c = tid&7; rows advance by 16 per i
    // (r&7 invariant across i) -> swizzled dst advances by +2048 per i.
    const int lr0 = tid >> 3, lc0 = tid & 7;
    const uint32_t sw0 = ((uint32_t)lr0 << 7) | ((uint32_t)(lc0 ^ (lr0 & 7)) << 4);
    const __nv_bfloat16* aSrc = g_xb  + ((size_t)(bt * BM + lr0)) * FDIM + lc0 * 8;
    const __nv_bfloat16* bSrc = g_locb + ((size_t)(ct * BN + lr0)) * FDIM + lc0 * 8;

    #define LOAD_TILE(buf, k0) do {                                              \
        uint32_t _ad = sbase + SM_ABUF(buf) + sw0;                               \
        uint32_t _bd = sbase + SM_BBUF(buf) + sw0;                               \
        const __nv_bfloat16* _as = aSrc + (k0);                                  \
        const __nv_bfloat16* _bs = bSrc + (k0);                                  \
        _Pragma("unroll")                                                        \
        for (int _i = 0; _i < 8; _i++) {                                         \
            cp16(_ad + _i * 2048, _as + (size_t)_i * 16 * FDIM);                 \
            cp16(_bd + _i * 2048, _bs + (size_t)_i * 16 * FDIM);                 \
        }                                                                        \
    } while (0)

    // prologue: prefetch chunks 0 and 1
    LOAD_TILE(0, 0 * BK);
    CP_COMMIT();
    LOAD_TILE(1, 1 * BK);
    CP_COMMIT();

    // per-lane ldmatrix base offsets (ks=0); K-step advance is XOR (ks<<5)
    const int mat = lane >> 3, rin = lane & 7;
    uint32_t aoff[4], boff[4];
    #pragma unroll
    for (int mi = 0; mi < 4; mi++) {
        int row = wm * 64 + mi * 16 + (mat & 1) * 8 + rin;
        aoff[mi] = ((uint32_t)row << 7) | ((uint32_t)((mat >> 1) ^ (row & 7)) << 4);
    }
    #pragma unroll
    for (int ni2 = 0; ni2 < 4; ni2++) {
        int row = wn * 64 + ni2 * 16 + (mat & 1) * 8 + rin;
        boff[ni2] = ((uint32_t)row << 7) | ((uint32_t)((mat >> 1) ^ (row & 7)) << 4);
    }

    float acc[4][8][4];
    #pragma unroll
    for (int mi = 0; mi < 4; mi++)
        #pragma unroll
        for (int ni = 0; ni < 8; ni++)
            #pragma unroll
            for (int e = 0; e < 4; e++) acc[mi][ni][e] = 0.f;

    // ---------------- K mainloop (double-buffered) ----------------
    for (int s = 0; s < KSTEPS; s++) {
        const int buf = s & 1;
        CP_WAIT1();          // chunk s resident for this thread
        __syncthreads();     // ... and for all threads

        const uint32_t abase = sbase + SM_ABUF(buf);
        const uint32_t bbase = sbase + SM_BBUF(buf);
        #pragma unroll
        for (int ks = 0; ks < BK / 16; ks++) {
            uint32_t a[4][4], b[4][4];
            #pragma unroll
            for (int mi = 0; mi < 4; mi++)
                LDSM4(a[mi][0], a[mi][1], a[mi][2], a[mi][3],
                      abase + (aoff[mi] ^ ((uint32_t)ks << 5)));   // XOR advance
            #pragma unroll
            for (int ni2 = 0; ni2 < 4; ni2++)
                LDSM4(b[ni2][0], b[ni2][1], b[ni2][2], b[ni2][3],
                      bbase + (boff[ni2] ^ ((uint32_t)ks << 5)));  // XOR advance
            #pragma unroll
            for (int mi = 0; mi < 4; mi++)
                #pragma unroll
                for (int ni2 = 0; ni2 < 4; ni2++) {
                    mma_bf16(acc[mi][ni2 * 2 + 0], a[mi], b[ni2][0], b[ni2][2]);
                    mma_bf16(acc[mi][ni2 * 2 + 1], a[mi], b[ni2][1], b[ni2][3]);
                }
        }
        __syncthreads();     // all warps done reading buf before overwrite

        if (s + 2 < KSTEPS) LOAD_TILE(buf, (s + 2) * BK);
        CP_COMMIT();         // exactly one group per iteration (maybe empty)
    }

    // zero sout (aliases dead A0 buffer)
    float* sout = (float*)smem;   // [128][10]
    for (int i = tid; i < BM * ODIM; i += THREADS) sout[i] = 0.f;
    __syncthreads();

    // ---------------- fused epilogue ----------------
    const int lr = lane >> 2;         // 0..7
    const int lc = (lane & 3) * 2;    // 0,2,4,6
    #pragma unroll
    for (int mi = 0; mi < 4; mi++) {
        float p0[ODIM], p1[ODIM];
        #pragma unroll
        for (int o = 0; o < ODIM; o++) { p0[o] = 0.f; p1[o] = 0.f; }
        const int r0 = wm * 64 + mi * 16 + lr;   // local row; r1 = r0+8
        const float xx0 = x2s[r0];
        const float xx1 = x2s[r0 + 8];
        #pragma unroll
        for (int ni = 0; ni < 8; ni++) {
            #pragma unroll
            for (int j = 0; j < 2; j++) {
                const int cl = wn * 64 + ni * 8 + lc + j;
                const float2 ci = c2iv[cl];
                const float s0 = acc[mi][ni][j];
                const float s1 = acc[mi][ni][2 + j];
                const float d0 = sqrtf(fmaxf(fmaf(-2.0f, s0, xx0 + ci.x), 0.f));
                const float d1 = sqrtf(fmaxf(fmaf(-2.0f, s1, xx1 + ci.x), 0.f));
                const float ph0 = __expf(-d0 * ci.y);
                const float ph1 = __expf(-d1 * ci.y);
                const float4 w0 = *(const float4*)&wpack[cl * 12];
                const float4 w1 = *(const float4*)&wpack[cl * 12 + 4];
                const float2 w2 = *(const float2*)&wpack[cl * 12 + 8];
                p0[0] = fmaf(ph0, w0.x, p0[0]);  p1[0] = fmaf(ph1, w0.x, p1[0]);
                p0[1] = fmaf(ph0, w0.y, p0[1]);  p1[1] = fmaf(ph1, w0.y, p1[1]);
                p0[2] = fmaf(ph0, w0.z, p0[2]);  p1[2] = fmaf(ph1, w0.z, p1[2]);
                p0[3] = fmaf(ph0, w0.w, p0[3]);  p1[3] = fmaf(ph1, w0.w, p1[3]);
                p0[4] = fmaf(ph0, w1.x, p0[4]);  p1[4] = fmaf(ph1, w1.x, p1[4]);
                p0[5] = fmaf(ph0, w1.y, p0[5]);  p1[5] = fmaf(ph1, w1.y, p1[5]);
                p0[6] = fmaf(ph0, w1.z, p0[6]);  p1[6] = fmaf(ph1, w1.z, p1[6]);
                p0[7] = fmaf(ph0, w1.w, p0[7]);  p1[7] = fmaf(ph1, w1.w, p1[7]);
                p0[8] = fmaf(ph0, w2.x, p0[8]);  p1[8] = fmaf(ph1, w2.x, p1[8]);
                p0[9] = fmaf(ph0, w2.y, p0[9]);  p1[9] = fmaf(ph1, w2.y, p1[9]);
            }
        }
        // reduce across the 4 lanes sharing a row
        #pragma unroll
        for (int o = 0; o < ODIM; o++) {
            p0[o] += __shfl_xor_sync(0xffffffffu, p0[o], 1);
            p0[o] += __shfl_xor_sync(0xffffffffu, p0[o], 2);
            p1[o] += __shfl_xor_sync(0xffffffffu, p1[o], 1);
            p1[o] += __shfl_xor_sync(0xffffffffu, p1[o], 2);
        }
        if ((lane & 3) == 0) {
            // exactly 2 contributors per cell (wn=0,1): commutative -> deterministic
            #pragma unroll
            for (int o = 0; o < ODIM; o++) {
                atomicAdd(&sout[r0 * ODIM + o], p0[o]);
                atomicAdd(&sout[(r0 + 8) * ODIM + o], p1[o]);
            }
        }
    }
    __syncthreads();

    // write deterministic per-c-tile partials
    for (int i = tid; i < BM * ODIM; i += THREADS) {
        int r = i / ODIM, o = i % ODIM;
        g_partial[(size_t)ct * (BATCH * ODIM) + (size_t)(bt * BM + r) * ODIM + o] = sout[i];
    }
}

// ---------------- final reduce over c-tiles ----------------
__global__ void reduce_out_kernel(float* __restrict__ out) {
    int i = blockIdx.x * 256 + threadIdx.x;
    if (i < BATCH * ODIM) {
        float s = 0.f;
        #pragma unroll
        for (int ctl = 0; ctl < NCT; ctl++) s += g_partial[(size_t)ctl * (BATCH * ODIM) + i];
        out[i] = s;
    }
}

// ---------------- launcher ----------------
extern "C" void kernel_launch(void* const* d_in, const int* in_sizes, int n_in,
                              void* d_out, int out_size) {
    const float* x     = (const float*)d_in[0];  // [8192,1024]
    const float* loc   = (const float*)d_in[1];  // [4096,1024]
    const float* scale = (const float*)d_in[2];  // [4096]
    const float* w     = (const float*)d_in[3];  // [10,4096]
    float* out = (float*)d_out;                  // [8192,10]

    cudaFuncSetAttribute(rbf_main_kernel,
                         cudaFuncAttributeMaxDynamicSharedMemorySize, SMEM_TOTAL);

    conv_x_kernel<<<BATCH, 256>>>(x);
    conv_loc_kernel<<<CDIM, 256>>>(loc);
    invs_kernel<<<(CDIM + 255) / 256, 256>>>(scale);

    dim3 grid(NBT, NCT);
    rbf_main_kernel<<<grid, THREADS, SMEM_TOTAL>>>(w);

    reduce_out_kernel<<<(BATCH * ODIM + 255) / 256, 256>>>(out);
}

// round 14
// speedup vs baseline: 1.0051x; 1.0051x over previous
#include <cuda_runtime.h>
#include <cuda_bf16.h>
#include <cstdint>

// ---------------- problem constants ----------------
#define BATCH 8192
#define CDIM  4096
#define FDIM  1024
#define ODIM  10

// ---------------- tile config ----------------
#define BM 128
#define BN 128
#define BK 64                 // bf16 elements per K chunk (= 128 bytes per row)
#define KSTEPS (FDIM / BK)    // 16 chunks
#define NCT (CDIM / BN)       // 32 c-tiles
#define NBT (BATCH / BM)      // 64 b-tiles
#define THREADS 256           // 8 warps as 4(m) x 2(n), warp tile 32x64
#define NSTAGE 3

// ---------------- smem layout (bytes, dynamic) ----------------
#define SM_ABUF(b)  ((b) * 32768)
#define SM_BBUF(b)  ((b) * 32768 + 16384)
#define SM_WPACK    (NSTAGE * 32768)        // float [128][12]  (w repacked, padded)
#define SM_C2IV     (SM_WPACK + 6144)       // float2 [128] (c2, 1/scale)
#define SM_X2       (SM_C2IV + 1024)        // float  [128]
#define SMEM_TOTAL  (SM_X2 + 512)           // 105984 B -> 2 CTAs/SM (212KB of 228KB)
// sout (float[128][10]) reuses the dead buffer-0 after the mainloop.

// -------- scratch (device globals; allocation-free) --------
__device__ __nv_bfloat16 g_xb[(size_t)BATCH * FDIM];   // 16 MB
__device__ __nv_bfloat16 g_locb[(size_t)CDIM * FDIM];  //  8 MB
__device__ float g_x2[BATCH];
__device__ float g_c2[CDIM];
__device__ float g_invs[CDIM];
__device__ float g_partial[(size_t)NCT * BATCH * ODIM]; // 10.5 MB

// ---------------- PTX helpers ----------------
__device__ __forceinline__ uint32_t smem_u32(const void* p) {
    uint32_t a;
    asm("{ .reg .u64 t; cvta.to.shared.u64 t, %1; cvt.u32.u64 %0, t; }" : "=r"(a) : "l"(p));
    return a;
}
__device__ __forceinline__ void cp16(uint32_t dst, const void* src) {
    asm volatile("cp.async.cg.shared.global [%0], [%1], 16;" :: "r"(dst), "l"(src));
}
#define CP_COMMIT() asm volatile("cp.async.commit_group;" ::: "memory")
#define CP_WAIT1()  asm volatile("cp.async.wait_group 1;" ::: "memory")

#define LDSM4(r0, r1, r2, r3, addr) \
    asm volatile("ldmatrix.sync.aligned.m8n8.x4.shared.b16 {%0,%1,%2,%3}, [%4];" \
                 : "=r"(r0), "=r"(r1), "=r"(r2), "=r"(r3) : "r"(addr))

__device__ __forceinline__ void mma_bf16(float c[4], const uint32_t a[4],
                                         uint32_t b0, uint32_t b1) {
    asm volatile(
        "mma.sync.aligned.m16n8k16.row.col.f32.bf16.bf16.f32 "
        "{%0,%1,%2,%3}, {%4,%5,%6,%7}, {%8,%9}, {%0,%1,%2,%3};\n"
        : "+f"(c[0]), "+f"(c[1]), "+f"(c[2]), "+f"(c[3])
        : "r"(a[0]), "r"(a[1]), "r"(a[2]), "r"(a[3]), "r"(b0), "r"(b1));
}

// ---------------- pre-pass: fp32 -> bf16 + row norms ----------------
__global__ void conv_x_kernel(const float* __restrict__ x) {
    int row = blockIdx.x, tid = threadIdx.x;
    float4 v = ((const float4*)(x + (size_t)row * FDIM))[tid];
    float s = v.x * v.x + v.y * v.y + v.z * v.z + v.w * v.w;
    __nv_bfloat162* d = (__nv_bfloat162*)(g_xb + (size_t)row * FDIM);
    d[tid * 2 + 0] = __floats2bfloat162_rn(v.x, v.y);
    d[tid * 2 + 1] = __floats2bfloat162_rn(v.z, v.w);
    #pragma unroll
    for (int off = 16; off; off >>= 1) s += __shfl_xor_sync(0xffffffffu, s, off);
    __shared__ float wsum[8];
    if ((tid & 31) == 0) wsum[tid >> 5] = s;
    __syncthreads();
    if (tid == 0) {
        float t = 0.f;
        #pragma unroll
        for (int i = 0; i < 8; i++) t += wsum[i];
        g_x2[row] = t;
    }
}

__global__ void conv_loc_kernel(const float* __restrict__ loc) {
    int row = blockIdx.x, tid = threadIdx.x;
    float4 v = ((const float4*)(loc + (size_t)row * FDIM))[tid];
    float s = v.x * v.x + v.y * v.y + v.z * v.z + v.w * v.w;
    __nv_bfloat162* d = (__nv_bfloat162*)(g_locb + (size_t)row * FDIM);
    d[tid * 2 + 0] = __floats2bfloat162_rn(v.x, v.y);
    d[tid * 2 + 1] = __floats2bfloat162_rn(v.z, v.w);
    #pragma unroll
    for (int off = 16; off; off >>= 1) s += __shfl_xor_sync(0xffffffffu, s, off);
    __shared__ float wsum[8];
    if ((tid & 31) == 0) wsum[tid >> 5] = s;
    __syncthreads();
    if (tid == 0) {
        float t = 0.f;
        #pragma unroll
        for (int i = 0; i < 8; i++) t += wsum[i];
        g_c2[row] = t;
    }
}

__global__ void invs_kernel(const float* __restrict__ scale) {
    int i = blockIdx.x * 256 + threadIdx.x;
    if (i < CDIM) g_invs[i] = 1.0f / scale[i];
}

// ---------------- main fused kernel: mma.sync + 3-stage cp.async ----------------
// CTA = 128x128 tile. 8 warps as 4(m) x 2(n): warp tile 32x64.
__global__ __launch_bounds__(THREADS, 2)
void rbf_main_kernel(const float* __restrict__ w) {
    extern __shared__ char smem[];
    const uint32_t sbase = smem_u32(smem);
    const int tid = threadIdx.x;
    const int lane = tid & 31;
    const int warp = tid >> 5;
    const int wm = warp & 3;    // m offset wm*32
    const int wn = warp >> 2;   // n offset wn*64
    const int bt = blockIdx.x;
    const int ct = blockIdx.y;

    // stage epilogue params into smem
    float*  wpack = (float*)(smem + SM_WPACK);   // [128][12]
    float2* c2iv  = (float2*)(smem + SM_C2IV);   // [128]
    float*  x2s   = (float*)(smem + SM_X2);      // [128]
    for (int i = tid; i < BN * ODIM; i += THREADS) {
        int c = i / ODIM, o = i % ODIM;
        wpack[c * 12 + o] = w[(size_t)o * CDIM + ct * BN + c];
    }
    if (tid < BN) c2iv[tid] = make_float2(g_c2[ct * BN + tid], g_invs[ct * BN + tid]);
    if (tid < BM) x2s[tid] = g_x2[bt * BM + tid];

    // ---- precomputed loader addressing (loop-invariant swizzle) ----
    // 256 threads: r0 = tid>>3 (0..31), c = tid&7; rows advance by 32 per i
    // (r&7 invariant) -> swizzled dst advances by +4096 per i; 4 iters per tile.
    const int lr0 = tid >> 3, lc0 = tid & 7;
    const uint32_t sw0 = ((uint32_t)lr0 << 7) | ((uint32_t)(lc0 ^ (lr0 & 7)) << 4);
    const __nv_bfloat16* aSrc = g_xb   + ((size_t)(bt * BM + lr0)) * FDIM + lc0 * 8;
    const __nv_bfloat16* bSrc = g_locb + ((size_t)(ct * BN + lr0)) * FDIM + lc0 * 8;

    #define LOAD_TILE(buf, k0) do {                                              \
        uint32_t _ad = sbase + SM_ABUF(buf) + sw0;                               \
        uint32_t _bd = sbase + SM_BBUF(buf) + sw0;                               \
        const __nv_bfloat16* _as = aSrc + (k0);                                  \
        const __nv_bfloat16* _bs = bSrc + (k0);                                  \
        _Pragma("unroll")                                                        \
        for (int _i = 0; _i < 4; _i++) {                                         \
            cp16(_ad + _i * 4096, _as + (size_t)_i * 32 * FDIM);                 \
            cp16(_bd + _i * 4096, _bs + (size_t)_i * 32 * FDIM);                 \
        }                                                                        \
    } while (0)

    // prologue: prefetch chunks 0 and 1 into stages 0 and 1
    LOAD_TILE(0, 0 * BK);
    CP_COMMIT();
    LOAD_TILE(1, 1 * BK);
    CP_COMMIT();

    // per-lane ldmatrix base offsets (ks=0); K-step advance is XOR (ks<<5)
    const int mat = lane >> 3, rin = lane & 7;
    uint32_t aoff[2], boff[4];
    #pragma unroll
    for (int mi = 0; mi < 2; mi++) {
        int row = wm * 32 + mi * 16 + (mat & 1) * 8 + rin;
        aoff[mi] = ((uint32_t)row << 7) | ((uint32_t)((mat >> 1) ^ (row & 7)) << 4);
    }
    #pragma unroll
    for (int ni2 = 0; ni2 < 4; ni2++) {
        int row = wn * 64 + ni2 * 16 + (mat & 1) * 8 + rin;
        boff[ni2] = ((uint32_t)row << 7) | ((uint32_t)((mat >> 1) ^ (row & 7)) << 4);
    }

    float acc[2][8][4];
    #pragma unroll
    for (int mi = 0; mi < 2; mi++)
        #pragma unroll
        for (int ni = 0; ni < 8; ni++)
            #pragma unroll
            for (int e = 0; e < 4; e++) acc[mi][ni][e] = 0.f;

    // ---------------- K mainloop (3-stage, ONE barrier per chunk) ----------------
    // At iter s: chunk s resident in stage s%3; chunk s+1 in flight; after the
    // barrier, stage (s+2)%3 == (s-1)%3 is free (all warps computed s-1 before
    // arriving here), so prefetch chunk s+2 into it, then compute chunk s.
    int bufC = 0;                       // s % 3
    int bufL = 2;                       // (s+2) % 3
    for (int s = 0; s < KSTEPS; s++) {
        CP_WAIT1();          // chunk s complete (<=1 group pending: chunk s+1)
        __syncthreads();     // visibility to all warps + frees stage bufL

        if (s + 2 < KSTEPS) LOAD_TILE(bufL, (s + 2) * BK);
        CP_COMMIT();         // exactly one group per iteration (maybe empty)

        const uint32_t abase = sbase + SM_ABUF(bufC);
        const uint32_t bbase = sbase + SM_BBUF(bufC);
        #pragma unroll
        for (int ks = 0; ks < BK / 16; ks++) {
            uint32_t a[2][4], b[4][4];
            #pragma unroll
            for (int mi = 0; mi < 2; mi++)
                LDSM4(a[mi][0], a[mi][1], a[mi][2], a[mi][3],
                      abase + (aoff[mi] ^ ((uint32_t)ks << 5)));   // XOR advance
            #pragma unroll
            for (int ni2 = 0; ni2 < 4; ni2++)
                LDSM4(b[ni2][0], b[ni2][1], b[ni2][2], b[ni2][3],
                      bbase + (boff[ni2] ^ ((uint32_t)ks << 5)));  // XOR advance
            #pragma unroll
            for (int mi = 0; mi < 2; mi++)
                #pragma unroll
                for (int ni2 = 0; ni2 < 4; ni2++) {
                    mma_bf16(acc[mi][ni2 * 2 + 0], a[mi], b[ni2][0], b[ni2][2]);
                    mma_bf16(acc[mi][ni2 * 2 + 1], a[mi], b[ni2][1], b[ni2][3]);
                }
        }

        bufC = (bufC == NSTAGE - 1) ? 0 : bufC + 1;
        bufL = (bufL == NSTAGE - 1) ? 0 : bufL + 1;
    }
    __syncthreads();   // last chunk's reads done before sout aliases stage 0

    // zero sout (aliases dead stage-0 buffer)
    float* sout = (float*)smem;   // [128][10]
    for (int i = tid; i < BM * ODIM; i += THREADS) sout[i] = 0.f;
    __syncthreads();

    // ---------------- fused epilogue ----------------
    const int lr = lane >> 2;         // 0..7
    const int lc = (lane & 3) * 2;    // 0,2,4,6
    #pragma unroll
    for (int mi = 0; mi < 2; mi++) {
        float p0[ODIM], p1[ODIM];
        #pragma unroll
        for (int o = 0; o < ODIM; o++) { p0[o] = 0.f; p1[o] = 0.f; }
        const int r0 = wm * 32 + mi * 16 + lr;   // local row; r1 = r0+8
        const float xx0 = x2s[r0];
        const float xx1 = x2s[r0 + 8];
        #pragma unroll
        for (int ni = 0; ni < 8; ni++) {
            #pragma unroll
            for (int j = 0; j < 2; j++) {
                const int cl = wn * 64 + ni * 8 + lc + j;
                const float2 ci = c2iv[cl];
                const float s0 = acc[mi][ni][j];
                const float s1 = acc[mi][ni][2 + j];
                const float d0 = sqrtf(fmaxf(fmaf(-2.0f, s0, xx0 + ci.x), 0.f));
                const float d1 = sqrtf(fmaxf(fmaf(-2.0f, s1, xx1 + ci.x), 0.f));
                const float ph0 = __expf(-d0 * ci.y);
                const float ph1 = __expf(-d1 * ci.y);
                const float4 w0 = *(const float4*)&wpack[cl * 12];
                const float4 w1 = *(const float4*)&wpack[cl * 12 + 4];
                const float2 w2 = *(const float2*)&wpack[cl * 12 + 8];
                p0[0] = fmaf(ph0, w0.x, p0[0]);  p1[0] = fmaf(ph1, w0.x, p1[0]);
                p0[1] = fmaf(ph0, w0.y, p0[1]);  p1[1] = fmaf(ph1, w0.y, p1[1]);
                p0[2] = fmaf(ph0, w0.z, p0[2]);  p1[2] = fmaf(ph1, w0.z, p1[2]);
                p0[3] = fmaf(ph0, w0.w, p0[3]);  p1[3] = fmaf(ph1, w0.w, p1[3]);
                p0[4] = fmaf(ph0, w1.x, p0[4]);  p1[4] = fmaf(ph1, w1.x, p1[4]);
                p0[5] = fmaf(ph0, w1.y, p0[5]);  p1[5] = fmaf(ph1, w1.y, p1[5]);
                p0[6] = fmaf(ph0, w1.z, p0[6]);  p1[6] = fmaf(ph1, w1.z, p1[6]);
                p0[7] = fmaf(ph0, w1.w, p0[7]);  p1[7] = fmaf(ph1, w1.w, p1[7]);
                p0[8] = fmaf(ph0, w2.x, p0[8]);  p1[8] = fmaf(ph1, w2.x, p1[8]);
                p0[9] = fmaf(ph0, w2.y, p0[9]);  p1[9] = fmaf(ph1, w2.y, p1[9]);
            }
        }
        // reduce across the 4 lanes sharing a row
        #pragma unroll
        for (int o = 0; o < ODIM; o++) {
            p0[o] += __shfl_xor_sync(0xffffffffu, p0[o], 1);
            p0[o] += __shfl_xor_sync(0xffffffffu, p0[o], 2);
            p1[o] += __shfl_xor_sync(0xffffffffu, p1[o], 1);
            p1[o] += __shfl_xor_sync(0xffffffffu, p1[o], 2);
        }
        if ((lane & 3) == 0) {
            // exactly 2 contributors per cell (wn=0,1): commutative -> deterministic
            #pragma unroll
            for (int o = 0; o < ODIM; o++) {
                atomicAdd(&sout[r0 * ODIM + o], p0[o]);
                atomicAdd(&sout[(r0 + 8) * ODIM + o], p1[o]);
            }
        }
    }
    __syncthreads();

    // write deterministic per-c-tile partials
    for (int i = tid; i < BM * ODIM; i += THREADS) {
        int r = i / ODIM, o = i % ODIM;
        g_partial[(size_t)ct * (BATCH * ODIM) + (size_t)(bt * BM + r) * ODIM + o] = sout[i];
    }
}

// ---------------- final reduce over c-tiles ----------------
__global__ void reduce_out_kernel(float* __restrict__ out) {
    int i = blockIdx.x * 256 + threadIdx.x;
    if (i < BATCH * ODIM) {
        float s = 0.f;
        #pragma unroll
        for (int ctl = 0; ctl < NCT; ctl++) s += g_partial[(size_t)ctl * (BATCH * ODIM) + i];
        out[i] = s;
    }
}

// ---------------- launcher ----------------
extern "C" void kernel_launch(void* const* d_in, const int* in_sizes, int n_in,
                              void* d_out, int out_size) {
    const float* x     = (const float*)d_in[0];  // [8192,1024]
    const float* loc   = (const float*)d_in[1];  // [4096,1024]
    const float* scale = (const float*)d_in[2];  // [4096]
    const float* w     = (const float*)d_in[3];  // [10,4096]
    float* out = (float*)d_out;                  // [8192,10]

    cudaFuncSetAttribute(rbf_main_kernel,
                         cudaFuncAttributeMaxDynamicSharedMemorySize, SMEM_TOTAL);

    conv_x_kernel<<<BATCH, 256>>>(x);
    conv_loc_kernel<<<CDIM, 256>>>(loc);
    invs_kernel<<<(CDIM + 255) / 256, 256>>>(scale);

    dim3 grid(NBT, NCT);
    rbf_main_kernel<<<grid, THREADS, SMEM_TOTAL>>>(w);

    reduce_out_kernel<<<(BATCH * ODIM + 255) / 256, 256>>>(out);
}